// round 6
// baseline (speedup 1.0000x reference)
#include <cuda_runtime.h>

typedef unsigned long long u64;

#define NL    16
#define CC    128
#define CP    (CC / 2)
#define EE    10
#define P3C   23
#define P2C   4
#define MAXN  4096
#define MB    16
#define SPLIT 4
#define NPOS  1120
#define NSLOT 160
#define NACT  136
#define PCB   (CC / 8 * EE)                 // 160 precompute blocks in K2
#define SYMB  ((NPOS * P3C + 319) / 320)    // 81 sym blocks in K1

// __device__ globals = sanctioned scratch. Channel-paired (packed f32x2) layouts.
__device__ __align__(16) float g_S[(size_t)EE * CP * NPOS * 2];
__device__ __align__(16) float g_Q[EE * CP * NSLOT * 2];
__device__ __align__(16) float g_L[EE * CP * NL * 2];
__device__ float g_U3S[NPOS * P3C];
__device__ __align__(16) float g_xT[(size_t)CP * MAXN * NL * 2];  // [cp][gpos][i][2]
__device__ int g_binsg[MAXN];
__device__ int g_pos[MAXN];
__device__ int g_counts[EE];
__device__ int g_offs[EE];

// ---- packed f32x2 helpers (only reachable via PTX) ------------------------
__device__ __forceinline__ u64 fma2(u64 a, u64 b, u64 c) {
    u64 d; asm("fma.rn.f32x2 %0, %1, %2, %3;" : "=l"(d) : "l"(a), "l"(b), "l"(c)); return d;
}
__device__ __forceinline__ u64 mul2(u64 a, u64 b) {
    u64 d; asm("mul.rn.f32x2 %0, %1, %2;" : "=l"(d) : "l"(a), "l"(b)); return d;
}
__device__ __forceinline__ u64 add2(u64 a, u64 b) {
    u64 d; asm("add.rn.f32x2 %0, %1, %2;" : "=l"(d) : "l"(a), "l"(b)); return d;
}

__device__ __forceinline__ void slot_ab(int s, int& a, int& b) {
    a = 0; b = 0;
    int off = 0;
#pragma unroll
    for (int aa = 15; aa >= 0; aa--) {
        int cnt = 16 - aa;
        if (s >= off && s < off + cnt) { a = aa; b = aa + (s - off); }
        off += cnt;
    }
}

__device__ __forceinline__ float u3at(const float* U3, int d0, int d1, int d2, int k) {
    return U3[((d0 * NL + d1) * NL + d2) * P3C + k];
}

// ---------------------------------------------------------------------------
// K1: blocks [0,SYMB) symmetrize U3; block SYMB bins atoms (with global pos).
// ---------------------------------------------------------------------------
__global__ __launch_bounds__(320) void k1_kernel(const float* __restrict__ U3,
                                                 const int* __restrict__ at, int N) {
    if (blockIdx.x < SYMB) {
        const int idx = blockIdx.x * 320 + threadIdx.x;
        if (idx >= NPOS * P3C) return;
        const int p = idx / P3C;
        const int k = idx - p * P3C;
        int base, ch;
        if      (p < 512)  { ch = 0; base = 0;    }
        else if (p < 800)  { ch = 1; base = 512;  }
        else if (p < 992)  { ch = 2; base = 800;  }
        else if (p < 1088) { ch = 3; base = 992;  }
        else               { ch = 4; base = 1088; }
        const int rel = p - base;
        const int j = rel >> 5;
        const int l = rel & 31;
        const int s = ch * 32 + l;
        float val = 0.f;
        if (s < NACT) {
            int a, b; slot_ab(s, a, b);
            const int i = j;
            if (i <= a) {
                float sum = u3at(U3, i, a, b, k) + u3at(U3, i, b, a, k)
                          + u3at(U3, a, i, b, k) + u3at(U3, a, b, i, k)
                          + u3at(U3, b, i, a, k) + u3at(U3, b, a, i, k);
                float r = (i == a && a == b) ? 6.f : ((i == a || a == b) ? 2.f : 1.f);
                val = sum / r;
            }
        }
        g_U3S[idx] = val;
        return;
    }

    // binning block
    __shared__ int ts[MAXN];
    __shared__ int scnt[EE], soff[EE];
    const int tid = threadIdx.x;
    for (int idx = tid; idx < N; idx += 320) ts[idx] = at[idx];
    __syncthreads();
    const int e = tid >> 5, lane = tid & 31;
    {
        int cnt = 0;
        for (int base = 0; base < N; base += 32) {
            int idx = base + lane;
            int t = (idx < N) ? ts[idx] : -1;
            cnt += __popc(__ballot_sync(0xffffffffu, t == e));
        }
        if (lane == 0) scnt[e] = cnt;
    }
    __syncthreads();
    if (tid == 0) {
        int acc = 0;
        for (int q = 0; q < EE; q++) { soff[q] = acc; acc += scnt[q]; }
    }
    __syncthreads();
    {
        int cnt = 0;
        const int off = soff[e];
        for (int base = 0; base < N; base += 32) {
            int idx = base + lane;
            int t = (idx < N) ? ts[idx] : -1;
            unsigned m = __ballot_sync(0xffffffffu, t == e);
            if (t == e) {
                int gp = off + cnt + __popc(m & ((1u << lane) - 1u));
                g_binsg[gp] = idx;
                g_pos[idx] = gp;
            }
            cnt += __popc(m);
        }
        if (lane == 0) { g_counts[e] = cnt; g_offs[e] = off; }
    }
}

// ---------------------------------------------------------------------------
// K2: blocks [0,PCB) contract U3S/U2/U1 with weights -> packed g_S/g_Q/g_L;
//     blocks [PCB, PCB+N) transpose x into bin-ordered channel-paired g_xT.
// ---------------------------------------------------------------------------
__global__ __launch_bounds__(256) void k2_kernel(const float* __restrict__ W3,
                                                 const float* __restrict__ U2,
                                                 const float* __restrict__ W2,
                                                 const float* __restrict__ U1,
                                                 const float* __restrict__ W1,
                                                 const float* __restrict__ x, int N) {
    __shared__ float sm[NL * (CC + 1)];
    const int tid = threadIdx.x;

    if (blockIdx.x < PCB) {
        const int c0 = (blockIdx.x & 15) * 8;
        const int e  = blockIdx.x >> 4;
        float* W3s = sm;                 // P3C*8
        float* W2s = sm + P3C * 8;       // P2C*8
        float* W1s = W2s + P2C * 8;      // 8
        for (int idx = tid; idx < P3C * 8; idx += 256) {
            int k = idx >> 3, cl = idx & 7;
            W3s[idx] = W3[(e * P3C + k) * CC + c0 + cl];
        }
        if (tid < P2C * 8) {
            int k = tid >> 3, cl = tid & 7;
            W2s[tid] = W2[(e * P2C + k) * CC + c0 + cl];
        }
        if (tid < 8) W1s[tid] = W1[e * CC + c0 + tid];
        __syncthreads();

        for (int p = tid; p < NPOS; p += 256) {
            float u[P3C];
#pragma unroll
            for (int k = 0; k < P3C; k++) u[k] = g_U3S[p * P3C + k];
#pragma unroll
            for (int cl = 0; cl < 8; cl++) {
                float acc = 0.f;
#pragma unroll
                for (int k = 0; k < P3C; k++) acc += u[k] * W3s[k * 8 + cl];
                const int c = c0 + cl;
                g_S[((size_t)(e * CP + (c >> 1)) * NPOS + p) * 2 + (c & 1)] = acc;
            }
        }
        if (tid < NSLOT) {
            const int s = tid;
            int a = 0, b = 0;
            const bool act = (s < NACT);
            if (act) slot_ab(s, a, b);
#pragma unroll
            for (int cl = 0; cl < 8; cl++) {
                float q = 0.f;
                if (act) {
                    float Bab = 0.f, Bba = 0.f;
#pragma unroll
                    for (int k = 0; k < P2C; k++) {
                        Bab += U2[(a * NL + b) * P2C + k] * W2s[k * 8 + cl];
                        Bba += U2[(b * NL + a) * P2C + k] * W2s[k * 8 + cl];
                    }
                    q = (a == b) ? Bab : (Bab + Bba);
                }
                const int c = c0 + cl;
                g_Q[((size_t)(e * CP + (c >> 1)) * NSLOT + s) * 2 + (c & 1)] = q;
            }
        }
        if (tid < NL) {
#pragma unroll
            for (int cl = 0; cl < 8; cl++) {
                const int c = c0 + cl;
                g_L[((size_t)(e * CP + (c >> 1)) * NL + tid) * 2 + (c & 1)] = U1[tid] * W1s[cl];
            }
        }
        return;
    }

    const int n = blockIdx.x - PCB;
    if (n >= N) return;
    for (int idx = tid; idx < NL * CC; idx += 256)
        sm[(idx / CC) * (CC + 1) + (idx % CC)] = x[(size_t)n * NL * CC + idx];
    __syncthreads();
    const int gp = g_pos[n];
    for (int idx = tid; idx < NL * CC; idx += 256) {
        const int cp = idx >> 5, r = idx & 31, i = r >> 1, ch = r & 1;
        g_xT[((size_t)cp * MAXN + gp) * 32 + r] = sm[i * (CC + 1) + (cp << 1) + ch];
    }
}

// ---------------------------------------------------------------------------
// K3: main contraction, packed f32x2 over channel pairs. 64 threads = 2 warps.
// ---------------------------------------------------------------------------
__global__ __launch_bounds__(64) void contract_kernel(float* __restrict__ out) {
    const int cp = blockIdx.x, e = blockIdx.y, z = blockIdx.z;
    const int t = threadIdx.x, w = t >> 5, lane = t & 31;

    __shared__ __align__(16) float2 xs2[MB][NL];
    __shared__ u64 red[MB][2];

    const int count = g_counts[e];
    const int goff  = g_offs[e];
    const int ntiles = (count + MB - 1) / MB;
    const int tpc    = (ntiles + SPLIT - 1) / SPLIT;
    const int begin  = min(count, z * tpc * MB);
    const int end    = min(count, begin + tpc * MB);
    const int nloc   = end - begin;
    if (nloc <= 0) return;

    const size_t ecp = (size_t)(e * CP + cp);
    const u64* Sp = (const u64*)g_S + ecp * NPOS;
    const u64* Qp = (const u64*)g_Q + ecp * NSLOT;
    const u64* Lp = (const u64*)g_L + ecp * NL;

    u64 kk[19];
    u64 q0, q1, q2 = 0;
    int a0, b0, a1, b1, a2 = 0, b2 = 0;
    if (w == 0) {
#pragma unroll
        for (int j = 0; j < 16; j++) kk[j] = Sp[j * 32 + lane];
#pragma unroll
        for (int j = 0; j < 3; j++) kk[16 + j] = Sp[992 + j * 32 + lane];
        q0 = Qp[lane];
        q1 = Qp[96 + lane];
        slot_ab(lane, a0, b0);
        slot_ab(96 + lane, a1, b1);
    } else {
#pragma unroll
        for (int j = 0; j < 9; j++) kk[j] = Sp[512 + j * 32 + lane];
#pragma unroll
        for (int j = 0; j < 6; j++) kk[9 + j] = Sp[800 + j * 32 + lane];
        kk[15] = Sp[1088 + lane];
        kk[16] = (lane < NL) ? Lp[lane] : 0ULL;
        q0 = Qp[32 + lane];
        q1 = Qp[64 + lane];
        q2 = Qp[128 + lane];
        slot_ab(32 + lane, a0, b0);
        slot_ab(64 + lane, a1, b1);
        if (128 + lane < NACT) slot_ab(128 + lane, a2, b2);
    }

    const float* xTc = g_xT + (size_t)cp * MAXN * 32;
    const int satm = t >> 2, part = t & 3;
    const int rowbase = goff + begin;

    float4 xr0 = make_float4(0.f, 0.f, 0.f, 0.f), xr1 = xr0;
    if (satm < nloc) {
        const float4* rp = (const float4*)(xTc + (size_t)(rowbase + satm) * 32);
        xr0 = rp[part]; xr1 = rp[part + 4];
    }

    const int mlane = ((lane >> 4) & 1) | (((lane >> 3) & 1) << 1)
                    | (((lane >> 2) & 1) << 2) | (((lane >> 1) & 1) << 3);
    const int xlin = lane & 15;

    for (int t0 = 0; t0 < nloc; t0 += MB) {
        const int rem = min(MB, nloc - t0);
        if (satm < rem) {
            float4* sp = (float4*)xs2[satm];
            sp[part] = xr0; sp[part + 4] = xr1;
        }
        __syncthreads();

        {
            const int nxt = t0 + MB + satm;
            if (nxt < nloc) {
                const float4* rp = (const float4*)(xTc + (size_t)(rowbase + nxt) * 32);
                xr0 = rp[part]; xr1 = rp[part + 4];
            }
        }

        u64 val[MB];
#pragma unroll
        for (int mm = 0; mm < MB; mm++) {
            const ulonglong2* xv = (const ulonglong2*)xs2[mm];
            const ulonglong2 p0 = xv[0], p1 = xv[1], p2 = xv[2], p3 = xv[3];
            const ulonglong2 p4 = xv[4], p5 = xv[5], p6 = xv[6], p7 = xv[7];
            const u64* xrow = (const u64*)xs2[mm];
            const u64 xa0 = xrow[a0], xb0 = xrow[b0];
            const u64 xa1 = xrow[a1], xb1 = xrow[b1];
            u64 v;
            if (w == 0) {
                u64 G0 = q0;
                G0 = fma2(kk[0],  p0.x, G0); G0 = fma2(kk[1],  p0.y, G0);
                G0 = fma2(kk[2],  p1.x, G0); G0 = fma2(kk[3],  p1.y, G0);
                G0 = fma2(kk[4],  p2.x, G0); G0 = fma2(kk[5],  p2.y, G0);
                G0 = fma2(kk[6],  p3.x, G0); G0 = fma2(kk[7],  p3.y, G0);
                G0 = fma2(kk[8],  p4.x, G0); G0 = fma2(kk[9],  p4.y, G0);
                G0 = fma2(kk[10], p5.x, G0); G0 = fma2(kk[11], p5.y, G0);
                G0 = fma2(kk[12], p6.x, G0); G0 = fma2(kk[13], p6.y, G0);
                G0 = fma2(kk[14], p7.x, G0); G0 = fma2(kk[15], p7.y, G0);
                u64 G1 = q1;
                G1 = fma2(kk[16], p0.x, G1); G1 = fma2(kk[17], p0.y, G1);
                G1 = fma2(kk[18], p1.x, G1);
                const u64 pr0 = mul2(xa0, xb0), pr1 = mul2(xa1, xb1);
                v = fma2(G1, pr1, mul2(G0, pr0));
            } else {
                u64 G0 = q0;
                G0 = fma2(kk[0], p0.x, G0); G0 = fma2(kk[1], p0.y, G0);
                G0 = fma2(kk[2], p1.x, G0); G0 = fma2(kk[3], p1.y, G0);
                G0 = fma2(kk[4], p2.x, G0); G0 = fma2(kk[5], p2.y, G0);
                G0 = fma2(kk[6], p3.x, G0); G0 = fma2(kk[7], p3.y, G0);
                G0 = fma2(kk[8], p4.x, G0);
                u64 G1 = q1;
                G1 = fma2(kk[9],  p0.x, G1); G1 = fma2(kk[10], p0.y, G1);
                G1 = fma2(kk[11], p1.x, G1); G1 = fma2(kk[12], p1.y, G1);
                G1 = fma2(kk[13], p2.x, G1); G1 = fma2(kk[14], p2.y, G1);
                const u64 G2 = fma2(kk[15], p0.x, q2);
                const u64 xa2v = xrow[a2], xb2v = xrow[b2];
                const u64 lin = mul2(kk[16], xrow[xlin]);
                const u64 pr0 = mul2(xa0, xb0), pr1 = mul2(xa1, xb1), pr2 = mul2(xa2v, xb2v);
                v = fma2(G0, pr0, fma2(G1, pr1, fma2(G2, pr2, lin)));
            }
            val[mm] = v;
        }

        // merged butterfly on packed values (R3/R4-validated structure)
        u64 m0[8];
#pragma unroll
        for (int k = 0; k < 8; k++) {
            const bool up = (lane & 16);
            u64 mine = up ? val[2 * k + 1] : val[2 * k];
            u64 oth  = up ? val[2 * k]     : val[2 * k + 1];
            m0[k] = add2(mine, __shfl_xor_sync(0xffffffffu, oth, 16));
        }
        u64 m1[4];
#pragma unroll
        for (int k = 0; k < 4; k++) {
            const bool up = (lane & 8);
            u64 mine = up ? m0[2 * k + 1] : m0[2 * k];
            u64 oth  = up ? m0[2 * k]     : m0[2 * k + 1];
            m1[k] = add2(mine, __shfl_xor_sync(0xffffffffu, oth, 8));
        }
        u64 m2[2];
#pragma unroll
        for (int k = 0; k < 2; k++) {
            const bool up = (lane & 4);
            u64 mine = up ? m1[2 * k + 1] : m1[2 * k];
            u64 oth  = up ? m1[2 * k]     : m1[2 * k + 1];
            m2[k] = add2(mine, __shfl_xor_sync(0xffffffffu, oth, 4));
        }
        {
            const bool up = (lane & 2);
            u64 mine = up ? m2[1] : m2[0];
            u64 oth  = up ? m2[0] : m2[1];
            u64 m3 = add2(mine, __shfl_xor_sync(0xffffffffu, oth, 2));
            m3 = add2(m3, __shfl_xor_sync(0xffffffffu, m3, 1));
            if ((lane & 1) == 0) red[mlane][w] = m3;
        }
        __syncthreads();

        if (t < rem) {
            const int id = g_binsg[rowbase + t0 + t];
            *(u64*)(out + (size_t)id * CC + 2 * cp) = add2(red[t][0], red[t][1]);
        }
        __syncthreads();
    }
}

// ---------------------------------------------------------------------------
extern "C" void kernel_launch(void* const* d_in, const int* in_sizes, int n_in,
                              void* d_out, int out_size) {
    const float* x  = (const float*)d_in[0];
    const int*   at = (const int*)d_in[1];
    const float* U3 = (const float*)d_in[2];
    const float* U2 = (const float*)d_in[3];
    const float* U1 = (const float*)d_in[4];
    const float* W3 = (const float*)d_in[5];
    const float* W2 = (const float*)d_in[6];
    const float* W1 = (const float*)d_in[7];
    float* out = (float*)d_out;
    const int N = in_sizes[1];

    k1_kernel<<<SYMB + 1, 320>>>(U3, at, N);
    k2_kernel<<<PCB + N, 256>>>(W3, U2, W2, U1, W1, x, N);
    contract_kernel<<<dim3(CP, EE, SPLIT), 64>>>(out);
}

// round 7
// speedup vs baseline: 1.2930x; 1.2930x over previous
#include <cuda_runtime.h>

#define NL    16
#define CC    128
#define EE    10
#define P3C   23
#define P2C   4
#define MAXN  4096
#define MB    16
#define SPLIT 4
#define NPOS  1120
#define NSLOT 160
#define NACT  136
#define PCB   (CC / 8 * EE)                      // 160 coeff blocks in K2
#define SYMB  ((NPOS * P3C + 1023) / 1024)       // 26 sym blocks in K1

// __device__ globals = sanctioned scratch.
__device__ float g_S[(size_t)EE * CC * NPOS];    // symmetrized cubic coeffs
__device__ float g_Q[EE * CC * NSLOT];
__device__ float g_L[EE * CC * NL];
__device__ float g_U3S[NPOS * P3C];
__device__ __align__(16) float g_xT[(size_t)CC * MAXN * NL];  // [c][gpos][i]
__device__ int g_binsg[MAXN];
__device__ int g_pos[MAXN];
__device__ int g_counts[EE];
__device__ int g_offs[EE];

__device__ __forceinline__ void slot_ab(int s, int& a, int& b) {
    a = 0; b = 0;
    int off = 0;
#pragma unroll
    for (int aa = 15; aa >= 0; aa--) {
        int cnt = 16 - aa;
        if (s >= off && s < off + cnt) { a = aa; b = aa + (s - off); }
        off += cnt;
    }
}

__device__ __forceinline__ float u3at(const float* U3, int d0, int d1, int d2, int k) {
    return U3[((d0 * NL + d1) * NL + d2) * P3C + k];
}

// ---------------------------------------------------------------------------
// K1: blocks [0,SYMB) symmetrize U3; block SYMB does parallel binning.
// ---------------------------------------------------------------------------
__global__ __launch_bounds__(1024) void k1_kernel(const float* __restrict__ U3,
                                                  const int* __restrict__ at, int N) {
    if (blockIdx.x < SYMB) {
        const int idx = blockIdx.x * 1024 + threadIdx.x;
        if (idx >= NPOS * P3C) return;
        const int p = idx / P3C;
        const int k = idx - p * P3C;
        int base, ch;
        if      (p < 512)  { ch = 0; base = 0;    }
        else if (p < 800)  { ch = 1; base = 512;  }
        else if (p < 992)  { ch = 2; base = 800;  }
        else if (p < 1088) { ch = 3; base = 992;  }
        else               { ch = 4; base = 1088; }
        const int rel = p - base;
        const int j = rel >> 5;
        const int l = rel & 31;
        const int s = ch * 32 + l;
        float val = 0.f;
        if (s < NACT) {
            int a, b; slot_ab(s, a, b);
            const int i = j;
            if (i <= a) {
                float sum = u3at(U3, i, a, b, k) + u3at(U3, i, b, a, k)
                          + u3at(U3, a, i, b, k) + u3at(U3, a, b, i, k)
                          + u3at(U3, b, i, a, k) + u3at(U3, b, a, i, k);
                float r = (i == a && a == b) ? 6.f : ((i == a || a == b) ? 2.f : 1.f);
                val = sum / r;
            }
        }
        g_U3S[idx] = val;
        return;
    }

    // ---- binning block: 30 active warps = (type, third) ----
    __shared__ int ts[MAXN];
    __shared__ int pcnt[32], pstart[32];
    const int tid = threadIdx.x;
    for (int idx = tid; idx < N; idx += 1024) ts[idx] = at[idx];
    __syncthreads();

    const int w = tid >> 5, lane = tid & 31;
    const int tp = w / 3, third = w % 3;
    const int D  = ((N + 2) / 3 + 31) & ~31;
    const int lo = third * D;
    const int hi = min(N, lo + D);

    if (w < 30) {
        int cnt = 0;
        for (int base = lo; base < hi; base += 32) {
            int idx = base + lane;
            int t = (idx < hi) ? ts[idx] : -1;
            cnt += __popc(__ballot_sync(0xffffffffu, t == tp));
        }
        if (lane == 0) pcnt[w] = cnt;
    }
    __syncthreads();
    if (tid == 0) {
        int acc = 0;
        for (int q = 0; q < EE; q++) {
            const int tot = pcnt[q * 3] + pcnt[q * 3 + 1] + pcnt[q * 3 + 2];
            g_offs[q] = acc;
            g_counts[q] = tot;
            pstart[q * 3]     = acc;
            pstart[q * 3 + 1] = acc + pcnt[q * 3];
            pstart[q * 3 + 2] = acc + pcnt[q * 3] + pcnt[q * 3 + 1];
            acc += tot;
        }
    }
    __syncthreads();
    if (w < 30) {
        int cnt = pstart[w];
        for (int base = lo; base < hi; base += 32) {
            int idx = base + lane;
            int t = (idx < hi) ? ts[idx] : -1;
            unsigned m = __ballot_sync(0xffffffffu, t == tp);
            if (t == tp) {
                int gp = cnt + __popc(m & ((1u << lane) - 1u));
                g_binsg[gp] = idx;
                g_pos[idx] = gp;
            }
            cnt += __popc(m);
        }
    }
}

// ---------------------------------------------------------------------------
// K2: blocks [0,PCB) coeff contraction; blocks [PCB,PCB+N) bin-ordered
//     vectorized transpose x[n][i][c] -> g_xT[c][gpos][i].
// ---------------------------------------------------------------------------
__global__ __launch_bounds__(256) void k2_kernel(const float* __restrict__ W3,
                                                 const float* __restrict__ U2,
                                                 const float* __restrict__ W2,
                                                 const float* __restrict__ U1,
                                                 const float* __restrict__ W1,
                                                 const float* __restrict__ x, int N) {
    __shared__ float sm[NL * 132];
    const int tid = threadIdx.x;

    if (blockIdx.x < PCB) {
        const int c0 = (blockIdx.x & 15) * 8;
        const int e  = blockIdx.x >> 4;
        float* W3s = sm;
        float* W2s = sm + P3C * 8;
        float* W1s = W2s + P2C * 8;
        for (int idx = tid; idx < P3C * 8; idx += 256) {
            int k = idx >> 3, cl = idx & 7;
            W3s[idx] = W3[(e * P3C + k) * CC + c0 + cl];
        }
        if (tid < P2C * 8) {
            int k = tid >> 3, cl = tid & 7;
            W2s[tid] = W2[(e * P2C + k) * CC + c0 + cl];
        }
        if (tid < 8) W1s[tid] = W1[e * CC + c0 + tid];
        __syncthreads();

        for (int p = tid; p < NPOS; p += 256) {
            float u[P3C];
#pragma unroll
            for (int k = 0; k < P3C; k++) u[k] = g_U3S[p * P3C + k];
#pragma unroll
            for (int cl = 0; cl < 8; cl++) {
                float acc = 0.f;
#pragma unroll
                for (int k = 0; k < P3C; k++) acc += u[k] * W3s[k * 8 + cl];
                g_S[((size_t)(e * CC + c0 + cl)) * NPOS + p] = acc;
            }
        }
        if (tid < NSLOT) {
            const int s = tid;
            int a = 0, b = 0;
            const bool act = (s < NACT);
            if (act) slot_ab(s, a, b);
#pragma unroll
            for (int cl = 0; cl < 8; cl++) {
                float q = 0.f;
                if (act) {
                    float Bab = 0.f, Bba = 0.f;
#pragma unroll
                    for (int k = 0; k < P2C; k++) {
                        Bab += U2[(a * NL + b) * P2C + k] * W2s[k * 8 + cl];
                        Bba += U2[(b * NL + a) * P2C + k] * W2s[k * 8 + cl];
                    }
                    q = (a == b) ? Bab : (Bab + Bba);
                }
                g_Q[(size_t)(e * CC + c0 + cl) * NSLOT + s] = q;
            }
        }
        if (tid < NL) {
#pragma unroll
            for (int cl = 0; cl < 8; cl++)
                g_L[(size_t)(e * CC + c0 + cl) * NL + tid] = U1[tid] * W1s[cl];
        }
        return;
    }

    // ---- transpose block: one atom, float4 in / float4 out ----
    const int n = blockIdx.x - PCB;
    if (n >= N) return;
    const float4* xin = (const float4*)(x + (size_t)n * NL * CC);
#pragma unroll
    for (int q = 0; q < 2; q++) {
        const int v  = q * 256 + tid;          // 512 float4s
        const int i  = v >> 5;
        const int f4 = v & 31;
        *(float4*)(sm + i * 132 + f4 * 4) = xin[v];
    }
    __syncthreads();
    const int gp = g_pos[n];
    const int c  = tid >> 1;
    const int h  = tid & 1;
    float* orow = g_xT + ((size_t)c * MAXN + gp) * NL + h * 8;
    float4 o0, o1;
    o0.x = sm[(h * 8 + 0) * 132 + c]; o0.y = sm[(h * 8 + 1) * 132 + c];
    o0.z = sm[(h * 8 + 2) * 132 + c]; o0.w = sm[(h * 8 + 3) * 132 + c];
    o1.x = sm[(h * 8 + 4) * 132 + c]; o1.y = sm[(h * 8 + 5) * 132 + c];
    o1.z = sm[(h * 8 + 6) * 132 + c]; o1.w = sm[(h * 8 + 7) * 132 + c];
    ((float4*)orow)[0] = o0;
    ((float4*)orow)[1] = o1;
}

// ---------------------------------------------------------------------------
// K3: main contraction (R4-validated scalar form), bin-ordered contiguous
//     tile loads, no index indirection in the hot loop.
// ---------------------------------------------------------------------------
__global__ __launch_bounds__(64) void contract_kernel(float* __restrict__ out) {
    const int c = blockIdx.x, e = blockIdx.y, z = blockIdx.z;
    const int t = threadIdx.x;
    const int w = t >> 5, lane = t & 31;

    __shared__ __align__(16) float xs[MB][NL];
    __shared__ float red[MB][2];

    const int count  = g_counts[e];
    const int goff   = g_offs[e];
    const int ntiles = (count + MB - 1) / MB;
    const int tpc    = (ntiles + SPLIT - 1) / SPLIT;
    const int begin  = min(count, z * tpc * MB);
    const int end    = min(count, begin + tpc * MB);
    const int nloc   = end - begin;
    if (nloc <= 0) return;

    const size_t ec = (size_t)e * CC + c;
    const float* Sp = g_S + ec * NPOS;
    const float* Qp = g_Q + ec * NSLOT;
    const float* Lp = g_L + ec * NL;

    float kk[19];
    float q0, q1, q2 = 0.f;
    int a0, b0, a1, b1, a2 = 0, b2 = 0;
    if (w == 0) {
#pragma unroll
        for (int j = 0; j < 16; j++) kk[j] = Sp[j * 32 + lane];
#pragma unroll
        for (int j = 0; j < 3; j++) kk[16 + j] = Sp[992 + j * 32 + lane];
        q0 = Qp[lane];
        q1 = Qp[96 + lane];
        slot_ab(lane, a0, b0);
        slot_ab(96 + lane, a1, b1);
    } else {
#pragma unroll
        for (int j = 0; j < 9; j++) kk[j] = Sp[512 + j * 32 + lane];
#pragma unroll
        for (int j = 0; j < 6; j++) kk[9 + j] = Sp[800 + j * 32 + lane];
        kk[15] = Sp[1088 + lane];
        kk[16] = (lane < NL) ? Lp[lane] : 0.f;
        q0 = Qp[32 + lane];
        q1 = Qp[64 + lane];
        q2 = Qp[128 + lane];
        slot_ab(32 + lane, a0, b0);
        slot_ab(64 + lane, a1, b1);
        if (128 + lane < NACT) slot_ab(128 + lane, a2, b2);
    }

    const int rowbase = goff + begin;
    const float* xTc = g_xT + ((size_t)c * MAXN + rowbase) * NL;

    const int satm = t >> 2;   // staged atom
    const int sq   = t & 3;    // staged quarter
    float4 xr = make_float4(0.f, 0.f, 0.f, 0.f);
    if (satm < nloc)
        xr = ((const float4*)xTc)[satm * 4 + sq];   // 1KB contiguous tile

    const int mlane = ((lane >> 4) & 1) | (((lane >> 3) & 1) << 1)
                    | (((lane >> 2) & 1) << 2) | (((lane >> 1) & 1) << 3);
    const int xlin = lane & 15;

    for (int t0 = 0; t0 < nloc; t0 += MB) {
        const int rem = min(MB, nloc - t0);
        if (satm < rem)
            ((float4*)xs[satm])[sq] = xr;
        __syncthreads();

        {
            const int nxt = t0 + MB + satm;
            if (nxt < nloc)
                xr = ((const float4*)xTc)[nxt * 4 + sq];
        }

        float val[MB];
#pragma unroll
        for (int mm = 0; mm < MB; mm++) {
            const float4* xv = (const float4*)xs[mm];
            const float4 X0 = xv[0], X1 = xv[1], X2 = xv[2], X3 = xv[3];
            float v;
            if (w == 0) {
                float G0 = q0;
                G0 = fmaf(kk[0],  X0.x, G0); G0 = fmaf(kk[1],  X0.y, G0);
                G0 = fmaf(kk[2],  X0.z, G0); G0 = fmaf(kk[3],  X0.w, G0);
                G0 = fmaf(kk[4],  X1.x, G0); G0 = fmaf(kk[5],  X1.y, G0);
                G0 = fmaf(kk[6],  X1.z, G0); G0 = fmaf(kk[7],  X1.w, G0);
                G0 = fmaf(kk[8],  X2.x, G0); G0 = fmaf(kk[9],  X2.y, G0);
                G0 = fmaf(kk[10], X2.z, G0); G0 = fmaf(kk[11], X2.w, G0);
                G0 = fmaf(kk[12], X3.x, G0); G0 = fmaf(kk[13], X3.y, G0);
                G0 = fmaf(kk[14], X3.z, G0); G0 = fmaf(kk[15], X3.w, G0);
                float G1 = q1;
                G1 = fmaf(kk[16], X0.x, G1); G1 = fmaf(kk[17], X0.y, G1);
                G1 = fmaf(kk[18], X0.z, G1);
                v = G0 * xs[mm][a0] * xs[mm][b0]
                  + G1 * xs[mm][a1] * xs[mm][b1];
            } else {
                float G0 = q0;
                G0 = fmaf(kk[0], X0.x, G0); G0 = fmaf(kk[1], X0.y, G0);
                G0 = fmaf(kk[2], X0.z, G0); G0 = fmaf(kk[3], X0.w, G0);
                G0 = fmaf(kk[4], X1.x, G0); G0 = fmaf(kk[5], X1.y, G0);
                G0 = fmaf(kk[6], X1.z, G0); G0 = fmaf(kk[7], X1.w, G0);
                G0 = fmaf(kk[8], X2.x, G0);
                float G1 = q1;
                G1 = fmaf(kk[9],  X0.x, G1); G1 = fmaf(kk[10], X0.y, G1);
                G1 = fmaf(kk[11], X0.z, G1); G1 = fmaf(kk[12], X0.w, G1);
                G1 = fmaf(kk[13], X1.x, G1); G1 = fmaf(kk[14], X1.y, G1);
                float G2 = fmaf(kk[15], X0.x, q2);
                v = G0 * xs[mm][a0] * xs[mm][b0]
                  + G1 * xs[mm][a1] * xs[mm][b1]
                  + G2 * xs[mm][a2] * xs[mm][b2]
                  + kk[16] * xs[mm][xlin];
            }
            val[mm] = v;
        }

        // merged butterfly: 16 atom-sums over 32 lanes (R3/R4-validated)
        float m0[8];
#pragma unroll
        for (int k = 0; k < 8; k++) {
            const bool up = (lane & 16);
            float mine = up ? val[2 * k + 1] : val[2 * k];
            float oth  = up ? val[2 * k]     : val[2 * k + 1];
            m0[k] = mine + __shfl_xor_sync(0xffffffffu, oth, 16);
        }
        float m1[4];
#pragma unroll
        for (int k = 0; k < 4; k++) {
            const bool up = (lane & 8);
            float mine = up ? m0[2 * k + 1] : m0[2 * k];
            float oth  = up ? m0[2 * k]     : m0[2 * k + 1];
            m1[k] = mine + __shfl_xor_sync(0xffffffffu, oth, 8);
        }
        float m2[2];
#pragma unroll
        for (int k = 0; k < 2; k++) {
            const bool up = (lane & 4);
            float mine = up ? m1[2 * k + 1] : m1[2 * k];
            float oth  = up ? m1[2 * k]     : m1[2 * k + 1];
            m2[k] = mine + __shfl_xor_sync(0xffffffffu, oth, 4);
        }
        {
            const bool up = (lane & 2);
            float mine = up ? m2[1] : m2[0];
            float oth  = up ? m2[0] : m2[1];
            float m3 = mine + __shfl_xor_sync(0xffffffffu, oth, 2);
            m3 += __shfl_xor_sync(0xffffffffu, m3, 1);
            if ((lane & 1) == 0) red[mlane][w] = m3;
        }
        __syncthreads();

        if (t < rem) {
            const int id = g_binsg[rowbase + t0 + t];
            out[(size_t)id * CC + c] = red[t][0] + red[t][1];
        }
        __syncthreads();
    }
}

// ---------------------------------------------------------------------------
extern "C" void kernel_launch(void* const* d_in, const int* in_sizes, int n_in,
                              void* d_out, int out_size) {
    const float* x  = (const float*)d_in[0];
    const int*   at = (const int*)d_in[1];
    const float* U3 = (const float*)d_in[2];
    const float* U2 = (const float*)d_in[3];
    const float* U1 = (const float*)d_in[4];
    const float* W3 = (const float*)d_in[5];
    const float* W2 = (const float*)d_in[6];
    const float* W1 = (const float*)d_in[7];
    float* out = (float*)d_out;
    const int N = in_sizes[1];

    k1_kernel<<<SYMB + 1, 1024>>>(U3, at, N);
    k2_kernel<<<PCB + N, 256>>>(W3, U2, W2, U1, W1, x, N);
    contract_kernel<<<dim3(CC, EE, SPLIT), 64>>>(out);
}

// round 8
// speedup vs baseline: 1.3365x; 1.0337x over previous
#include <cuda_runtime.h>

typedef unsigned long long u64;

#define NL    16
#define CC    128
#define CP    (CC / 2)
#define EE    10
#define P3C   23
#define P2C   4
#define MAXN  4096
#define MB    16
#define SPLIT 4
#define NPOS  1120
#define NSLOT 160
#define NACT  136
#define PCB   (CC / 8 * EE)
#define SYMB  ((NPOS * P3C + 1023) / 1024)

// __device__ globals = sanctioned scratch.
__device__ float g_S[(size_t)EE * CC * NPOS];    // scalar coeffs (R6 layout)
__device__ float g_Q[EE * CC * NSLOT];
__device__ float g_L[EE * CC * NL];
__device__ float g_U3S[NPOS * P3C];
__device__ __align__(16) float g_xT[(size_t)CP * MAXN * NL * 2]; // [cp][gpos][i][2ch]
__device__ int g_binsg[MAXN];
__device__ int g_pos[MAXN];
__device__ int g_counts[EE];
__device__ int g_offs[EE];

// ---- packed f32x2 helpers -------------------------------------------------
__device__ __forceinline__ u64 fma2(u64 a, u64 b, u64 c) {
    u64 d; asm("fma.rn.f32x2 %0, %1, %2, %3;" : "=l"(d) : "l"(a), "l"(b), "l"(c)); return d;
}
__device__ __forceinline__ u64 mul2(u64 a, u64 b) {
    u64 d; asm("mul.rn.f32x2 %0, %1, %2;" : "=l"(d) : "l"(a), "l"(b)); return d;
}
__device__ __forceinline__ u64 add2(u64 a, u64 b) {
    u64 d; asm("add.rn.f32x2 %0, %1, %2;" : "=l"(d) : "l"(a), "l"(b)); return d;
}
__device__ __forceinline__ u64 pack2(float lo, float hi) {
    u64 d; asm("mov.b64 %0, {%1, %2};" : "=l"(d) : "f"(lo), "f"(hi)); return d;
}

__device__ __forceinline__ void slot_ab(int s, int& a, int& b) {
    a = 0; b = 0;
    int off = 0;
#pragma unroll
    for (int aa = 15; aa >= 0; aa--) {
        int cnt = 16 - aa;
        if (s >= off && s < off + cnt) { a = aa; b = aa + (s - off); }
        off += cnt;
    }
}

__device__ __forceinline__ float u3at(const float* U3, int d0, int d1, int d2, int k) {
    return U3[((d0 * NL + d1) * NL + d2) * P3C + k];
}

// ---------------------------------------------------------------------------
// K1: identical to R6 (sym blocks + parallel binning block).
// ---------------------------------------------------------------------------
__global__ __launch_bounds__(1024) void k1_kernel(const float* __restrict__ U3,
                                                  const int* __restrict__ at, int N) {
    if (blockIdx.x < SYMB) {
        const int idx = blockIdx.x * 1024 + threadIdx.x;
        if (idx >= NPOS * P3C) return;
        const int p = idx / P3C;
        const int k = idx - p * P3C;
        int base, ch;
        if      (p < 512)  { ch = 0; base = 0;    }
        else if (p < 800)  { ch = 1; base = 512;  }
        else if (p < 992)  { ch = 2; base = 800;  }
        else if (p < 1088) { ch = 3; base = 992;  }
        else               { ch = 4; base = 1088; }
        const int rel = p - base;
        const int j = rel >> 5;
        const int l = rel & 31;
        const int s = ch * 32 + l;
        float val = 0.f;
        if (s < NACT) {
            int a, b; slot_ab(s, a, b);
            const int i = j;
            if (i <= a) {
                float sum = u3at(U3, i, a, b, k) + u3at(U3, i, b, a, k)
                          + u3at(U3, a, i, b, k) + u3at(U3, a, b, i, k)
                          + u3at(U3, b, i, a, k) + u3at(U3, b, a, i, k);
                float r = (i == a && a == b) ? 6.f : ((i == a || a == b) ? 2.f : 1.f);
                val = sum / r;
            }
        }
        g_U3S[idx] = val;
        return;
    }

    __shared__ int ts[MAXN];
    __shared__ int pcnt[32], pstart[32];
    const int tid = threadIdx.x;
    for (int idx = tid; idx < N; idx += 1024) ts[idx] = at[idx];
    __syncthreads();

    const int w = tid >> 5, lane = tid & 31;
    const int tp = w / 3, third = w % 3;
    const int D  = ((N + 2) / 3 + 31) & ~31;
    const int lo = third * D;
    const int hi = min(N, lo + D);

    if (w < 30) {
        int cnt = 0;
        for (int base = lo; base < hi; base += 32) {
            int idx = base + lane;
            int t = (idx < hi) ? ts[idx] : -1;
            cnt += __popc(__ballot_sync(0xffffffffu, t == tp));
        }
        if (lane == 0) pcnt[w] = cnt;
    }
    __syncthreads();
    if (tid == 0) {
        int acc = 0;
        for (int q = 0; q < EE; q++) {
            const int tot = pcnt[q * 3] + pcnt[q * 3 + 1] + pcnt[q * 3 + 2];
            g_offs[q] = acc;
            g_counts[q] = tot;
            pstart[q * 3]     = acc;
            pstart[q * 3 + 1] = acc + pcnt[q * 3];
            pstart[q * 3 + 2] = acc + pcnt[q * 3] + pcnt[q * 3 + 1];
            acc += tot;
        }
    }
    __syncthreads();
    if (w < 30) {
        int cnt = pstart[w];
        for (int base = lo; base < hi; base += 32) {
            int idx = base + lane;
            int t = (idx < hi) ? ts[idx] : -1;
            unsigned m = __ballot_sync(0xffffffffu, t == tp);
            if (t == tp) {
                int gp = cnt + __popc(m & ((1u << lane) - 1u));
                g_binsg[gp] = idx;
                g_pos[idx] = gp;
            }
            cnt += __popc(m);
        }
    }
}

// ---------------------------------------------------------------------------
// K2: coeff blocks identical to R6; transpose blocks now write channel-paired
//     rows g_xT[cp][gpos][i][2] (64 x 128B full-sector segments per atom).
// ---------------------------------------------------------------------------
__global__ __launch_bounds__(256) void k2_kernel(const float* __restrict__ W3,
                                                 const float* __restrict__ U2,
                                                 const float* __restrict__ W2,
                                                 const float* __restrict__ U1,
                                                 const float* __restrict__ W1,
                                                 const float* __restrict__ x, int N) {
    __shared__ float sm[NL * 132];
    const int tid = threadIdx.x;

    if (blockIdx.x < PCB) {
        const int c0 = (blockIdx.x & 15) * 8;
        const int e  = blockIdx.x >> 4;
        float* W3s = sm;
        float* W2s = sm + P3C * 8;
        float* W1s = W2s + P2C * 8;
        for (int idx = tid; idx < P3C * 8; idx += 256) {
            int k = idx >> 3, cl = idx & 7;
            W3s[idx] = W3[(e * P3C + k) * CC + c0 + cl];
        }
        if (tid < P2C * 8) {
            int k = tid >> 3, cl = tid & 7;
            W2s[tid] = W2[(e * P2C + k) * CC + c0 + cl];
        }
        if (tid < 8) W1s[tid] = W1[e * CC + c0 + tid];
        __syncthreads();

        for (int p = tid; p < NPOS; p += 256) {
            float u[P3C];
#pragma unroll
            for (int k = 0; k < P3C; k++) u[k] = g_U3S[p * P3C + k];
#pragma unroll
            for (int cl = 0; cl < 8; cl++) {
                float acc = 0.f;
#pragma unroll
                for (int k = 0; k < P3C; k++) acc += u[k] * W3s[k * 8 + cl];
                g_S[((size_t)(e * CC + c0 + cl)) * NPOS + p] = acc;
            }
        }
        if (tid < NSLOT) {
            const int s = tid;
            int a = 0, b = 0;
            const bool act = (s < NACT);
            if (act) slot_ab(s, a, b);
#pragma unroll
            for (int cl = 0; cl < 8; cl++) {
                float q = 0.f;
                if (act) {
                    float Bab = 0.f, Bba = 0.f;
#pragma unroll
                    for (int k = 0; k < P2C; k++) {
                        Bab += U2[(a * NL + b) * P2C + k] * W2s[k * 8 + cl];
                        Bba += U2[(b * NL + a) * P2C + k] * W2s[k * 8 + cl];
                    }
                    q = (a == b) ? Bab : (Bab + Bba);
                }
                g_Q[(size_t)(e * CC + c0 + cl) * NSLOT + s] = q;
            }
        }
        if (tid < NL) {
#pragma unroll
            for (int cl = 0; cl < 8; cl++)
                g_L[(size_t)(e * CC + c0 + cl) * NL + tid] = U1[tid] * W1s[cl];
        }
        return;
    }

    // ---- transpose block: one atom ----
    const int n = blockIdx.x - PCB;
    if (n >= N) return;
    const float4* xin = (const float4*)(x + (size_t)n * NL * CC);
#pragma unroll
    for (int q = 0; q < 2; q++) {
        const int v  = q * 256 + tid;
        const int i  = v >> 5;
        const int f4 = v & 31;
        *(float4*)(sm + i * 132 + f4 * 4) = xin[v];
    }
    __syncthreads();
    const int gp = g_pos[n];
    const int cp = tid >> 2;     // 64 channel-pairs
    const int q  = tid & 3;      // quarter of the 32-float row
    const int c0 = 2 * cp;
    float* orow = g_xT + ((size_t)cp * MAXN + gp) * 32 + q * 8;
    float4 oA, oB;
    oA.x = sm[(4 * q + 0) * 132 + c0]; oA.y = sm[(4 * q + 0) * 132 + c0 + 1];
    oA.z = sm[(4 * q + 1) * 132 + c0]; oA.w = sm[(4 * q + 1) * 132 + c0 + 1];
    oB.x = sm[(4 * q + 2) * 132 + c0]; oB.y = sm[(4 * q + 2) * 132 + c0 + 1];
    oB.z = sm[(4 * q + 3) * 132 + c0]; oB.w = sm[(4 * q + 3) * 132 + c0 + 1];
    ((float4*)orow)[0] = oA;
    ((float4*)orow)[1] = oB;
}

// ---------------------------------------------------------------------------
// K3: packed-f32x2 contraction, 2 channels per CTA. Structure mirrors R6;
//     stage-1 butterfly merge fused into the mm loop (register control).
// ---------------------------------------------------------------------------
__global__ __launch_bounds__(64) void contract_kernel(float* __restrict__ out) {
    const int cp = blockIdx.x, e = blockIdx.y, z = blockIdx.z;
    const int t = threadIdx.x;
    const int w = t >> 5, lane = t & 31;

    __shared__ __align__(16) float xs[MB][32];   // [atom][i][2ch]
    __shared__ u64 red[MB][2];

    const int count  = g_counts[e];
    const int goff   = g_offs[e];
    const int ntiles = (count + MB - 1) / MB;
    const int tpc    = (ntiles + SPLIT - 1) / SPLIT;
    const int begin  = min(count, z * tpc * MB);
    const int end    = min(count, begin + tpc * MB);
    const int nloc   = end - begin;
    if (nloc <= 0) return;

    const float* Sp0 = g_S + ((size_t)e * CC + 2 * cp) * NPOS;
    const float* Sp1 = Sp0 + NPOS;
    const float* Qp0 = g_Q + ((size_t)e * CC + 2 * cp) * NSLOT;
    const float* Qp1 = Qp0 + NSLOT;
    const float* Lp0 = g_L + ((size_t)e * CC + 2 * cp) * NL;
    const float* Lp1 = Lp0 + NL;

    u64 kk[19];
    u64 q0, q1, q2 = 0;
    int a0, b0, a1, b1, a2 = 0, b2 = 0;
    if (w == 0) {
#pragma unroll
        for (int j = 0; j < 16; j++) kk[j] = pack2(Sp0[j * 32 + lane], Sp1[j * 32 + lane]);
#pragma unroll
        for (int j = 0; j < 3; j++)
            kk[16 + j] = pack2(Sp0[992 + j * 32 + lane], Sp1[992 + j * 32 + lane]);
        q0 = pack2(Qp0[lane], Qp1[lane]);
        q1 = pack2(Qp0[96 + lane], Qp1[96 + lane]);
        slot_ab(lane, a0, b0);
        slot_ab(96 + lane, a1, b1);
    } else {
#pragma unroll
        for (int j = 0; j < 9; j++) kk[j] = pack2(Sp0[512 + j * 32 + lane], Sp1[512 + j * 32 + lane]);
#pragma unroll
        for (int j = 0; j < 6; j++) kk[9 + j] = pack2(Sp0[800 + j * 32 + lane], Sp1[800 + j * 32 + lane]);
        kk[15] = pack2(Sp0[1088 + lane], Sp1[1088 + lane]);
        kk[16] = (lane < NL) ? pack2(Lp0[lane], Lp1[lane]) : 0ULL;
        q0 = pack2(Qp0[32 + lane], Qp1[32 + lane]);
        q1 = pack2(Qp0[64 + lane], Qp1[64 + lane]);
        q2 = pack2(Qp0[128 + lane], Qp1[128 + lane]);
        slot_ab(32 + lane, a0, b0);
        slot_ab(64 + lane, a1, b1);
        if (128 + lane < NACT) slot_ab(128 + lane, a2, b2);
    }

    const int rowbase = goff + begin;
    const float* xTc = g_xT + ((size_t)cp * MAXN + rowbase) * 32;

    const int satm = t >> 2;
    const int sq   = t & 3;
    float4 xrA = make_float4(0.f, 0.f, 0.f, 0.f), xrB = xrA;
    if (satm < nloc) {
        const float4* rp = (const float4*)(xTc + (size_t)satm * 32);
        xrA = rp[sq]; xrB = rp[sq + 4];
    }

    const int mlane = ((lane >> 4) & 1) | (((lane >> 3) & 1) << 1)
                    | (((lane >> 2) & 1) << 2) | (((lane >> 1) & 1) << 3);
    const int xlin = lane & 15;

    for (int t0 = 0; t0 < nloc; t0 += MB) {
        const int rem = min(MB, nloc - t0);
        if (satm < rem) {
            float4* sp = (float4*)xs[satm];
            sp[sq] = xrA; sp[sq + 4] = xrB;
        }
        __syncthreads();

        {
            const int nxt = t0 + MB + satm;
            if (nxt < nloc) {
                const float4* rp = (const float4*)(xTc + (size_t)nxt * 32);
                xrA = rp[sq]; xrB = rp[sq + 4];
            }
        }

        // fused compute + stage-1 merge (2 atoms per k) — bounds register life
        u64 m0[8];
#pragma unroll
        for (int k = 0; k < 8; k++) {
            u64 pv[2];
#pragma unroll
            for (int h = 0; h < 2; h++) {
                const int mm = 2 * k + h;
                const ulonglong2* xv = (const ulonglong2*)xs[mm];
                const u64* xrow = (const u64*)xs[mm];
                u64 v;
                if (w == 0) {
                    ulonglong2 P0 = xv[0], P1 = xv[1], P2 = xv[2], P3 = xv[3];
                    u64 G0 = q0;
                    G0 = fma2(kk[0],  P0.x, G0); G0 = fma2(kk[1],  P0.y, G0);
                    G0 = fma2(kk[2],  P1.x, G0); G0 = fma2(kk[3],  P1.y, G0);
                    ulonglong2 P4 = xv[4], P5 = xv[5];
                    G0 = fma2(kk[4],  P2.x, G0); G0 = fma2(kk[5],  P2.y, G0);
                    G0 = fma2(kk[6],  P3.x, G0); G0 = fma2(kk[7],  P3.y, G0);
                    ulonglong2 P6 = xv[6], P7 = xv[7];
                    G0 = fma2(kk[8],  P4.x, G0); G0 = fma2(kk[9],  P4.y, G0);
                    G0 = fma2(kk[10], P5.x, G0); G0 = fma2(kk[11], P5.y, G0);
                    G0 = fma2(kk[12], P6.x, G0); G0 = fma2(kk[13], P6.y, G0);
                    G0 = fma2(kk[14], P7.x, G0); G0 = fma2(kk[15], P7.y, G0);
                    u64 G1 = q1;
                    G1 = fma2(kk[16], P0.x, G1); G1 = fma2(kk[17], P0.y, G1);
                    G1 = fma2(kk[18], P1.x, G1);
                    const u64 pr0 = mul2(xrow[a0], xrow[b0]);
                    const u64 pr1 = mul2(xrow[a1], xrow[b1]);
                    v = fma2(G1, pr1, mul2(G0, pr0));
                } else {
                    ulonglong2 P0 = xv[0], P1 = xv[1], P2 = xv[2], P3 = xv[3];
                    ulonglong2 P4 = xv[4];
                    u64 G0 = q0;
                    G0 = fma2(kk[0], P0.x, G0); G0 = fma2(kk[1], P0.y, G0);
                    G0 = fma2(kk[2], P1.x, G0); G0 = fma2(kk[3], P1.y, G0);
                    G0 = fma2(kk[4], P2.x, G0); G0 = fma2(kk[5], P2.y, G0);
                    G0 = fma2(kk[6], P3.x, G0); G0 = fma2(kk[7], P3.y, G0);
                    G0 = fma2(kk[8], P4.x, G0);
                    u64 G1 = q1;
                    G1 = fma2(kk[9],  P0.x, G1); G1 = fma2(kk[10], P0.y, G1);
                    G1 = fma2(kk[11], P1.x, G1); G1 = fma2(kk[12], P1.y, G1);
                    G1 = fma2(kk[13], P2.x, G1); G1 = fma2(kk[14], P2.y, G1);
                    const u64 G2 = fma2(kk[15], P0.x, q2);
                    const u64 lin = mul2(kk[16], xrow[xlin]);
                    const u64 pr0 = mul2(xrow[a0], xrow[b0]);
                    const u64 pr1 = mul2(xrow[a1], xrow[b1]);
                    const u64 pr2 = mul2(xrow[a2], xrow[b2]);
                    v = fma2(G0, pr0, fma2(G1, pr1, fma2(G2, pr2, lin)));
                }
                pv[h] = v;
            }
            const bool up = (lane & 16);
            u64 mine = up ? pv[1] : pv[0];
            u64 oth  = up ? pv[0] : pv[1];
            m0[k] = add2(mine, __shfl_xor_sync(0xffffffffu, oth, 16));
        }
        u64 m1[4];
#pragma unroll
        for (int k = 0; k < 4; k++) {
            const bool up = (lane & 8);
            u64 mine = up ? m0[2 * k + 1] : m0[2 * k];
            u64 oth  = up ? m0[2 * k]     : m0[2 * k + 1];
            m1[k] = add2(mine, __shfl_xor_sync(0xffffffffu, oth, 8));
        }
        u64 m2[2];
#pragma unroll
        for (int k = 0; k < 2; k++) {
            const bool up = (lane & 4);
            u64 mine = up ? m1[2 * k + 1] : m1[2 * k];
            u64 oth  = up ? m1[2 * k]     : m1[2 * k + 1];
            m2[k] = add2(mine, __shfl_xor_sync(0xffffffffu, oth, 4));
        }
        {
            const bool up = (lane & 2);
            u64 mine = up ? m2[1] : m2[0];
            u64 oth  = up ? m2[0] : m2[1];
            u64 m3 = add2(mine, __shfl_xor_sync(0xffffffffu, oth, 2));
            m3 = add2(m3, __shfl_xor_sync(0xffffffffu, m3, 1));
            if ((lane & 1) == 0) red[mlane][w] = m3;
        }
        __syncthreads();

        if (t < rem) {
            const int id = g_binsg[rowbase + t0 + t];
            *(u64*)(out + (size_t)id * CC + 2 * cp) = add2(red[t][0], red[t][1]);
        }
        __syncthreads();
    }
}

// ---------------------------------------------------------------------------
extern "C" void kernel_launch(void* const* d_in, const int* in_sizes, int n_in,
                              void* d_out, int out_size) {
    const float* x  = (const float*)d_in[0];
    const int*   at = (const int*)d_in[1];
    const float* U3 = (const float*)d_in[2];
    const float* U2 = (const float*)d_in[3];
    const float* U1 = (const float*)d_in[4];
    const float* W3 = (const float*)d_in[5];
    const float* W2 = (const float*)d_in[6];
    const float* W1 = (const float*)d_in[7];
    float* out = (float*)d_out;
    const int N = in_sizes[1];

    k1_kernel<<<SYMB + 1, 1024>>>(U3, at, N);
    k2_kernel<<<PCB + N, 256>>>(W3, U2, W2, U1, W1, x, N);
    contract_kernel<<<dim3(CP, EE, SPLIT), 64>>>(out);
}